// round 12
// baseline (speedup 1.0000x reference)
#include <cuda_runtime.h>
#include <cuda_bf16.h>
#include <cstdint>

#define BATCH 16
#define LQ    512
#define LC    2048
#define DIM   1024

// ---------------------------------------------------------------------------
// Device scratch (device-side only; symbols NEVER passed from host)
// ---------------------------------------------------------------------------
__device__ float         g_attn[(size_t)BATCH * LC * LQ];     // fp32 logits
__device__ __nv_bfloat16 g_q_hi[(size_t)BATCH * LQ * DIM];
__device__ __nv_bfloat16 g_q_lo[(size_t)BATCH * LQ * DIM];
__device__ __nv_bfloat16 g_w_hi[(size_t)BATCH * LC * LQ];     // softmax weights
__device__ __nv_bfloat16 g_w_lo[(size_t)BATCH * LC * LQ];

// ---------------------------------------------------------------------------
// helpers
// ---------------------------------------------------------------------------
__device__ __forceinline__ void ldm4(uint32_t a, uint32_t& r0, uint32_t& r1,
                                     uint32_t& r2, uint32_t& r3) {
    asm volatile("ldmatrix.sync.aligned.m8n8.x4.shared.b16 {%0,%1,%2,%3}, [%4];"
                 : "=r"(r0), "=r"(r1), "=r"(r2), "=r"(r3) : "r"(a));
}
__device__ __forceinline__ void ldm4t(uint32_t a, uint32_t& r0, uint32_t& r1,
                                      uint32_t& r2, uint32_t& r3) {
    asm volatile("ldmatrix.sync.aligned.m8n8.x4.trans.shared.b16 {%0,%1,%2,%3}, [%4];"
                 : "=r"(r0), "=r"(r1), "=r"(r2), "=r"(r3) : "r"(a));
}
__device__ __forceinline__ void mma16816(float* c, uint32_t a0, uint32_t a1, uint32_t a2,
                                         uint32_t a3, uint32_t b0, uint32_t b1) {
    asm volatile(
        "mma.sync.aligned.m16n8k16.row.col.f32.bf16.bf16.f32 "
        "{%0,%1,%2,%3}, {%4,%5,%6,%7}, {%8,%9}, {%0,%1,%2,%3};"
        : "+f"(c[0]), "+f"(c[1]), "+f"(c[2]), "+f"(c[3])
        : "r"(a0), "r"(a1), "r"(a2), "r"(a3), "r"(b0), "r"(b1));
}
__device__ __forceinline__ uint32_t smem_u32(const void* p) {
    uint32_t a;
    asm("{ .reg .u64 t; cvta.to.shared.u64 t, %1; cvt.u32.u64 %0, t; }" : "=r"(a) : "l"(p));
    return a;
}
__device__ __forceinline__ void cp16(uint32_t dst, const void* src) {
    asm volatile("cp.async.cg.shared.global [%0], [%1], 16;" :: "r"(dst), "l"(src));
}
__device__ __forceinline__ void cp_commit() { asm volatile("cp.async.commit_group;"); }
template <int N>
__device__ __forceinline__ void cp_wait() { asm volatile("cp.async.wait_group %0;" :: "n"(N)); }

// split float4 into packed bf16 hi pair-words and lo pair-words
__device__ __forceinline__ void split4(float4 v, uint32_t& h01, uint32_t& h23,
                                       uint32_t& l01, uint32_t& l23) {
    __nv_bfloat16 hx = __float2bfloat16(v.x), hy = __float2bfloat16(v.y);
    __nv_bfloat16 hz = __float2bfloat16(v.z), hw = __float2bfloat16(v.w);
    float lx = v.x - __bfloat162float(hx), ly = v.y - __bfloat162float(hy);
    float lz = v.z - __bfloat162float(hz), lw = v.w - __bfloat162float(hw);
    __nv_bfloat162 H0(hx, hy), H1(hz, hw);
    __nv_bfloat162 L0 = __floats2bfloat162_rn(lx, ly), L1 = __floats2bfloat162_rn(lz, lw);
    h01 = *(uint32_t*)&H0; h23 = *(uint32_t*)&H1;
    l01 = *(uint32_t*)&L0; l23 = *(uint32_t*)&L1;
}

// ---------------------------------------------------------------------------
// Q pre-split: fp32 -> bf16 hi/lo (~6us)
// ---------------------------------------------------------------------------
__global__ __launch_bounds__(256)
void ba_split_q(const float* __restrict__ src)
{
    const size_t i = (size_t)blockIdx.x * 256 + threadIdx.x;   // float4 index
    float4 v = ((const float4*)src)[i];
    uint32_t h01, h23, l01, l23;
    split4(v, h01, h23, l01, l23);
    ((uint2*)g_q_hi)[i] = make_uint2(h01, h23);
    ((uint2*)g_q_lo)[i] = make_uint2(l01, l23);
}

// ---------------------------------------------------------------------------
// Split-bf16 mma GEMM: CTA 128x256, warp tile 64x64 (8 warps), BK=16,
// 4-stage cp.async pipeline, one barrier per K-tile.
// FIRST : logits[c][q] = ctx(fp32, A split in-loop via reg path) . q(pre-split)
//         -> g_attn              grid (LQ/256, LC/128, B)
// !FIRST: attn[c][d] = w(pre-split) . q(pre-split, B=[k][n]) -> out right half
//         + fused ctx 128x256 tile copy into out LEFT half.
//         grid (DIM/256, LC/128, B)
// ---------------------------------------------------------------------------
#define AROWB 48                   // 16 bf16 = 32B + 16B pad (conflict-free)
#define BROWB2 528                 // GEMM2 B rows: 256 bf16 = 512B + 16B pad
#define NSTAGE 4
// stage layouts
#define S1_AH 0
#define S1_AL (128 * AROWB)                    // 6144
#define S1_BH (2 * 128 * AROWB)                // 12288
#define S1_BL (S1_BH + 256 * AROWB)            // 24576
#define STAGE1 (S1_BL + 256 * AROWB)           // 36864
#define S2_AH 0
#define S2_AL (128 * AROWB)
#define S2_BH (2 * 128 * AROWB)
#define S2_BL (S2_BH + 16 * BROWB2)            // 20736
#define STAGE2 (S2_BL + 16 * BROWB2)           // 29184

template <bool FIRST>
__global__ __launch_bounds__(256)
void ba_mma(const float* __restrict__ actx, float* __restrict__ gout)
{
    constexpr int KT = FIRST ? DIM : LQ;
    constexpr int NT = KT / 16;
    constexpr int OUTSTRIDE = FIRST ? LQ : 2 * DIM;
    constexpr int OUTOFF    = FIRST ? 0  : DIM;
    constexpr int STAGE = FIRST ? STAGE1 : STAGE2;
    constexpr int AH = 0, AL = 128 * AROWB;
    constexpr int BH = 2 * 128 * AROWB;
    constexpr int BL = FIRST ? S1_BL : S2_BL;

    extern __shared__ __align__(16) char sm[];
    const uint32_t sb = smem_u32(sm);

    const int tid  = threadIdx.x;
    const int lane = tid & 31;
    const int warp = tid >> 5;
    const int wm   = warp & 1;         // m offset 64*wm
    const int wn   = warp >> 1;        // n offset 64*wn (0..3)
    const int b  = blockIdx.z;
    const int yT = blockIdx.y;
    const int xT = blockIdx.x;

    // DEVICE-SIDE scratch binding
    const float* Abase_f = actx + ((size_t)b * LC + (size_t)yT * 128) * DIM;  // GEMM1 A (fp32 ctx)
    const char*  Awh = (const char*)g_w_hi + ((size_t)b * LC + (size_t)yT * 128) * LQ * 2;
    const char*  Awl = (const char*)g_w_lo + ((size_t)b * LC + (size_t)yT * 128) * LQ * 2;
    const char *Bqh, *Bql;
    if (FIRST) {   // B rows = q index (k-major)
        Bqh = (const char*)g_q_hi + ((size_t)b * LQ + (size_t)xT * 256) * DIM * 2;
        Bql = (const char*)g_q_lo + ((size_t)b * LQ + (size_t)xT * 256) * DIM * 2;
    } else {       // B = [k=q][n=d]
        Bqh = (const char*)g_q_hi + ((size_t)b * LQ * DIM + (size_t)xT * 256) * 2;
        Bql = (const char*)g_q_lo + ((size_t)b * LQ * DIM + (size_t)xT * 256) * 2;
    }

    // ---- loader coordinates ----
    // GEMM1 A fp32 reg path: rows ar, ar+64; float4 chunk ac
    const int ar = tid >> 2, ac = tid & 3;
    // GEMM1 B: row = tid (0..255), two 16B chunks
    // GEMM2 A: row = tid>>1 (0..127), chunk (tid&1)*16
    const int ar2 = tid >> 1, ac2 = (tid & 1) * 16;
    // GEMM2 B: k-rows tid>>5 and +8, col chunk (tid&31)*16
    const int kr2 = tid >> 5, nc2 = (tid & 31) * 16;

    float4 pa0, pa1;   // GEMM1 A prefetch

    auto ldgA = [&](int kt) {
        pa0 = *(const float4*)(Abase_f + (size_t)ar * DIM + kt * 16 + ac * 4);
        pa1 = *(const float4*)(Abase_f + (size_t)(ar + 64) * DIM + kt * 16 + ac * 4);
    };
    auto stsA = [&](int slot) {
        const uint32_t s0 = slot * STAGE;
        uint32_t h0, h1, l0, l1;
        split4(pa0, h0, h1, l0, l1);
        *(uint2*)(sm + (s0 + AH + ar * AROWB + ac * 8))        = make_uint2(h0, h1);
        *(uint2*)(sm + (s0 + AL + ar * AROWB + ac * 8))        = make_uint2(l0, l1);
        split4(pa1, h0, h1, l0, l1);
        *(uint2*)(sm + (s0 + AH + (ar + 64) * AROWB + ac * 8)) = make_uint2(h0, h1);
        *(uint2*)(sm + (s0 + AL + (ar + 64) * AROWB + ac * 8)) = make_uint2(l0, l1);
    };
    auto cp_stage = [&](int slot, int kt) {
        const uint32_t s0 = sb + slot * STAGE;
        if (FIRST) {
            // B: 256 rows x 32B (hi & lo): thread -> row tid, both chunks
            const size_t g = (size_t)tid * (DIM * 2) + (size_t)kt * 32;
            const uint32_t so = tid * AROWB;
            cp16(s0 + BH + so,      Bqh + g);
            cp16(s0 + BH + so + 16, Bqh + g + 16);
            cp16(s0 + BL + so,      Bql + g);
            cp16(s0 + BL + so + 16, Bql + g + 16);
        } else {
            // A(w): 128 rows x 32B hi/lo
            const size_t ga = (size_t)ar2 * (LQ * 2) + (size_t)kt * 32 + ac2;
            cp16(s0 + AH + ar2 * AROWB + ac2, Awh + ga);
            cp16(s0 + AL + ar2 * AROWB + ac2, Awl + ga);
            // B(q): 16 k-rows x 512B hi/lo
            const size_t gb0 = (size_t)(kt * 16 + kr2) * (DIM * 2) + nc2;
            const size_t gb1 = (size_t)(kt * 16 + kr2 + 8) * (DIM * 2) + nc2;
            cp16(s0 + BH + kr2 * BROWB2 + nc2,       Bqh + gb0);
            cp16(s0 + BH + (kr2 + 8) * BROWB2 + nc2, Bqh + gb1);
            cp16(s0 + BL + kr2 * BROWB2 + nc2,       Bql + gb0);
            cp16(s0 + BL + (kr2 + 8) * BROWB2 + nc2, Bql + gb1);
        }
        cp_commit();
    };

    float acc[4][8][4];
#pragma unroll
    for (int m = 0; m < 4; m++)
#pragma unroll
        for (int n = 0; n < 8; n++)
#pragma unroll
            for (int j = 0; j < 4; j++) acc[m][n][j] = 0.f;

    // ---- prologue: A(0) via reg path, B stages 0..2 via cp.async ----
    if (FIRST) { ldgA(0); stsA(0); }
    cp_stage(0, 0);
    cp_stage(1, 1);
    cp_stage(2, 2);

    const int lrow = lane & 15;
    const int lkb  = lane & 16;         // second 16B chunk (k+8 / n+8)
    constexpr int I1 = FIRST ? 2 : 1;   // ntile0 second b-reg
    constexpr int J0 = FIRST ? 1 : 2;   // ntile1 first b-reg

    for (int kt = 0; kt < NT; kt++) {
        cp_wait<2>();                   // stage kt's cp.async data arrived
        __syncthreads();                // publish stage kt (incl. A STS from body kt-1)

        if (FIRST && kt + 1 < NT) ldgA(kt + 1);
        if (kt + 3 < NT) cp_stage((kt + 3) % NSTAGE, kt + 3);
        else             cp_commit();   // keep group-count invariant

        const uint32_t s0 = (kt % NSTAGE) * STAGE;

        uint32_t ahf[4][4], alf[4][4];
#pragma unroll
        for (int mt = 0; mt < 4; mt++) {
            uint32_t ra = sb + s0 + AH + (wm * 64 + mt * 16 + lrow) * AROWB + lkb;
            ldm4(ra, ahf[mt][0], ahf[mt][1], ahf[mt][2], ahf[mt][3]);
            uint32_t rl = sb + s0 + AL + (wm * 64 + mt * 16 + lrow) * AROWB + lkb;
            ldm4(rl, alf[mt][0], alf[mt][1], alf[mt][2], alf[mt][3]);
        }
#pragma unroll
        for (int p = 0; p < 4; p++) {   // 4 n16 groups -> 8 n8 tiles
            uint32_t bh[4], bl[4];
            if (FIRST) {
                uint32_t rb = sb + s0 + BH + (wn * 64 + p * 16 + lrow) * AROWB + lkb;
                ldm4(rb, bh[0], bh[1], bh[2], bh[3]);
                uint32_t rc = sb + s0 + BL + (wn * 64 + p * 16 + lrow) * AROWB + lkb;
                ldm4(rc, bl[0], bl[1], bl[2], bl[3]);
            } else {
                uint32_t rb = sb + s0 + BH + lrow * BROWB2 + (wn * 64 + p * 16) * 2 + lkb;
                ldm4t(rb, bh[0], bh[1], bh[2], bh[3]);
                uint32_t rc = sb + s0 + BL + lrow * BROWB2 + (wn * 64 + p * 16) * 2 + lkb;
                ldm4t(rc, bl[0], bl[1], bl[2], bl[3]);
            }
#pragma unroll
            for (int mt = 0; mt < 4; mt++) {
                mma16816(acc[mt][2 * p],     ahf[mt][0], ahf[mt][1], ahf[mt][2], ahf[mt][3], bh[0],  bh[I1]);
                mma16816(acc[mt][2 * p + 1], ahf[mt][0], ahf[mt][1], ahf[mt][2], ahf[mt][3], bh[J0], bh[3]);
                mma16816(acc[mt][2 * p],     alf[mt][0], alf[mt][1], alf[mt][2], alf[mt][3], bh[0],  bh[I1]);
                mma16816(acc[mt][2 * p + 1], alf[mt][0], alf[mt][1], alf[mt][2], alf[mt][3], bh[J0], bh[3]);
                mma16816(acc[mt][2 * p],     ahf[mt][0], ahf[mt][1], ahf[mt][2], ahf[mt][3], bl[0],  bl[I1]);
                mma16816(acc[mt][2 * p + 1], ahf[mt][0], ahf[mt][1], ahf[mt][2], ahf[mt][3], bl[J0], bl[3]);
            }
        }

        if (FIRST && kt + 1 < NT) stsA((kt + 1) % NSTAGE);   // published by next barrier
    }

    // ---- epilogue (standard m16n8 C layout) ----
    float* Cg = FIRST ? (float*)g_attn : gout;
    const size_t rbase = (size_t)b * LC + (size_t)yT * 128 + wm * 64 + (lane >> 2);
    const int    cbase = OUTOFF + xT * 256 + wn * 64 + (lane & 3) * 2;
#pragma unroll
    for (int mt = 0; mt < 4; mt++) {
#pragma unroll
        for (int nt = 0; nt < 8; nt++) {
            size_t r0 = (rbase + mt * 16) * OUTSTRIDE + cbase + nt * 8;
            *(float2*)(Cg + r0)                    = make_float2(acc[mt][nt][0], acc[mt][nt][1]);
            *(float2*)(Cg + r0 + 8ull * OUTSTRIDE) = make_float2(acc[mt][nt][2], acc[mt][nt][3]);
        }
    }

    // fused ctx copy into out LEFT half (GEMM2 only): this CTA's 128x256 tile
    if (!FIRST) {
        const float4* csrc = (const float4*)(actx + ((size_t)b * LC + (size_t)yT * 128) * DIM
                                             + (size_t)xT * 256);
        float4* cdst = (float4*)(gout + ((size_t)b * LC + (size_t)yT * 128) * (2 * DIM)
                                 + (size_t)xT * 256);
        const int crow = tid >> 6;      // 0..3
        const int ccol = tid & 63;      // 64 float4 = 256 floats
#pragma unroll
        for (int it = 0; it < 32; it++) {
            cdst[(size_t)(crow + it * 4) * (2 * DIM / 4) + ccol] =
                csrc[(size_t)(crow + it * 4) * (DIM / 4) + ccol];
        }
    }
}

// ---------------------------------------------------------------------------
// Warp-per-row softmax over 512 logits: fp32 in (g_attn), bf16 hi/lo out (g_w).
// ---------------------------------------------------------------------------
__global__ __launch_bounds__(256)
void ba_softmax(void)
{
    const int wid = threadIdx.x >> 5, lane = threadIdx.x & 31;
    const size_t row = (size_t)blockIdx.x * 8 + wid;
    const float4* p = (const float4*)(g_attn + row * LQ);

    float4 v[4];
    float mx = -1e30f;
#pragma unroll
    for (int i = 0; i < 4; i++) {
        v[i] = p[i * 32 + lane];
        mx = fmaxf(mx, fmaxf(fmaxf(v[i].x, v[i].y), fmaxf(v[i].z, v[i].w)));
    }
#pragma unroll
    for (int o = 16; o > 0; o >>= 1) mx = fmaxf(mx, __shfl_xor_sync(0xFFFFFFFFu, mx, o));

    float sum = 0.f;
#pragma unroll
    for (int i = 0; i < 4; i++) {
        v[i].x = __expf(v[i].x - mx); v[i].y = __expf(v[i].y - mx);
        v[i].z = __expf(v[i].z - mx); v[i].w = __expf(v[i].w - mx);
        sum += (v[i].x + v[i].y) + (v[i].z + v[i].w);
    }
#pragma unroll
    for (int o = 16; o > 0; o >>= 1) sum += __shfl_xor_sync(0xFFFFFFFFu, sum, o);

    const float inv = 1.0f / sum;
    uint2* ph = (uint2*)(g_w_hi + row * LQ);
    uint2* pl = (uint2*)(g_w_lo + row * LQ);
#pragma unroll
    for (int i = 0; i < 4; i++) {
        v[i].x *= inv; v[i].y *= inv; v[i].z *= inv; v[i].w *= inv;
        uint32_t h01, h23, l01, l23;
        split4(v[i], h01, h23, l01, l23);
        ph[i * 32 + lane] = make_uint2(h01, h23);
        pl[i * 32 + lane] = make_uint2(l01, l23);
    }
}

// ---------------------------------------------------------------------------
extern "C" void kernel_launch(void* const* d_in, const int* in_sizes, int n_in,
                              void* d_out, int out_size)
{
    const float* question = (const float*)d_in[0];
    const float* context  = (const float*)d_in[1];
    if (in_sizes[0] > in_sizes[1]) {
        const float* t = question; question = context; context = t;
    }
    float* out = (float*)d_out;

    cudaFuncSetAttribute(ba_mma<true>,  cudaFuncAttributeMaxDynamicSharedMemorySize, NSTAGE * STAGE1);
    cudaFuncSetAttribute(ba_mma<false>, cudaFuncAttributeMaxDynamicSharedMemorySize, NSTAGE * STAGE2);

    // pre-split Q (small, ~6us)
    ba_split_q<<<(size_t)BATCH * LQ * DIM / 4 / 256, 256>>>(question);

    // logits = ctx @ q^T -> g_attn
    ba_mma<true><<<dim3(LQ / 256, LC / 128, BATCH), 256, NSTAGE * STAGE1>>>(context, nullptr);
    // softmax -> bf16 hi/lo weights
    ba_softmax<<<BATCH * LC / 8, 256>>>();
    // attn_out = w @ q -> right half of out, + fused ctx copy -> left half
    ba_mma<false><<<dim3(DIM / 256, LC / 128, BATCH), 256, NSTAGE * STAGE2>>>(context, out);
}

// round 13
// speedup vs baseline: 1.2001x; 1.2001x over previous
#include <cuda_runtime.h>
#include <cuda_bf16.h>
#include <cstdint>

#define BATCH 16
#define LQ    512
#define LC    2048
#define DIM   1024

// ---------------------------------------------------------------------------
// Device scratch (device-side only; symbols NEVER passed from host)
// ---------------------------------------------------------------------------
__device__ float         g_attn[(size_t)BATCH * LC * LQ];     // fp32 logits
__device__ __nv_bfloat16 g_q_hi[(size_t)BATCH * LQ * DIM];
__device__ __nv_bfloat16 g_q_lo[(size_t)BATCH * LQ * DIM];
__device__ __nv_bfloat16 g_w_hi[(size_t)BATCH * LC * LQ];     // softmax weights
__device__ __nv_bfloat16 g_w_lo[(size_t)BATCH * LC * LQ];

// ---------------------------------------------------------------------------
// helpers
// ---------------------------------------------------------------------------
__device__ __forceinline__ void ldm4(uint32_t a, uint32_t& r0, uint32_t& r1,
                                     uint32_t& r2, uint32_t& r3) {
    asm volatile("ldmatrix.sync.aligned.m8n8.x4.shared.b16 {%0,%1,%2,%3}, [%4];"
                 : "=r"(r0), "=r"(r1), "=r"(r2), "=r"(r3) : "r"(a));
}
__device__ __forceinline__ void ldm4t(uint32_t a, uint32_t& r0, uint32_t& r1,
                                      uint32_t& r2, uint32_t& r3) {
    asm volatile("ldmatrix.sync.aligned.m8n8.x4.trans.shared.b16 {%0,%1,%2,%3}, [%4];"
                 : "=r"(r0), "=r"(r1), "=r"(r2), "=r"(r3) : "r"(a));
}
__device__ __forceinline__ void mma16816(float* c, uint32_t a0, uint32_t a1, uint32_t a2,
                                         uint32_t a3, uint32_t b0, uint32_t b1) {
    asm volatile(
        "mma.sync.aligned.m16n8k16.row.col.f32.bf16.bf16.f32 "
        "{%0,%1,%2,%3}, {%4,%5,%6,%7}, {%8,%9}, {%0,%1,%2,%3};"
        : "+f"(c[0]), "+f"(c[1]), "+f"(c[2]), "+f"(c[3])
        : "r"(a0), "r"(a1), "r"(a2), "r"(a3), "r"(b0), "r"(b1));
}
__device__ __forceinline__ uint32_t smem_u32(const void* p) {
    uint32_t a;
    asm("{ .reg .u64 t; cvta.to.shared.u64 t, %1; cvt.u32.u64 %0, t; }" : "=r"(a) : "l"(p));
    return a;
}
// split float4 into packed bf16 hi pair-words and lo pair-words
__device__ __forceinline__ void split4(float4 v, uint32_t& h01, uint32_t& h23,
                                       uint32_t& l01, uint32_t& l23) {
    __nv_bfloat16 hx = __float2bfloat16(v.x), hy = __float2bfloat16(v.y);
    __nv_bfloat16 hz = __float2bfloat16(v.z), hw = __float2bfloat16(v.w);
    float lx = v.x - __bfloat162float(hx), ly = v.y - __bfloat162float(hy);
    float lz = v.z - __bfloat162float(hz), lw = v.w - __bfloat162float(hw);
    __nv_bfloat162 H0(hx, hy), H1(hz, hw);
    __nv_bfloat162 L0 = __floats2bfloat162_rn(lx, ly), L1 = __floats2bfloat162_rn(lz, lw);
    h01 = *(uint32_t*)&H0; h23 = *(uint32_t*)&H1;
    l01 = *(uint32_t*)&L0; l23 = *(uint32_t*)&L1;
}

// ---------------------------------------------------------------------------
// Q pre-split: fp32 -> bf16 hi/lo (~6us)
// ---------------------------------------------------------------------------
__global__ __launch_bounds__(256)
void ba_split_q(const float* __restrict__ src)
{
    const size_t i = (size_t)blockIdx.x * 256 + threadIdx.x;   // float4 index
    float4 v = ((const float4*)src)[i];
    uint32_t h01, h23, l01, l23;
    split4(v, h01, h23, l01, l23);
    ((uint2*)g_q_hi)[i] = make_uint2(h01, h23);
    ((uint2*)g_q_lo)[i] = make_uint2(l01, l23);
}

// ---------------------------------------------------------------------------
// Split-bf16 mma GEMM: CTA 128x128, 4 warps (128 threads), warp tile 64x64,
// BK=16, double-buffered static smem, register-prefetch loaders.
// __launch_bounds__(128, 2): 256 regs/thread available at 2 CTAs/SM, so the
// 128-reg accumulator + frags fit WITHOUT spills (R12's 256-thread 64x64
// variant spilled at the 1-CTA/255-reg wall; this is the resource-correct
// shape for the same smem-traffic-per-MMA win).
// FIRST : logits[c][q] = ctx(fp32, split in-loop) . q(pre-split)  -> g_attn
// !FIRST: attn[c][d] = w(pre-split) . q(pre-split, B=[k][n]) -> out right half
//         + fused ctx 128x128 tile copy into out LEFT half.
// ---------------------------------------------------------------------------
#define AROWB 48                   // 16 bf16 = 32B + 16B pad (conflict-free)
#define BROWB2 272                 // GEMM2 B rows: 256B + 16B pad

template <bool FIRST>
__global__ __launch_bounds__(128, 2)
void ba_mma(const float* __restrict__ actx, float* __restrict__ gout)
{
    constexpr int KT = FIRST ? DIM : LQ;
    constexpr int NT = KT / 16;
    constexpr int OUTSTRIDE = FIRST ? LQ : 2 * DIM;
    constexpr int OUTOFF    = FIRST ? 0  : DIM;
    constexpr int BHALF = FIRST ? (128 * AROWB) : (16 * BROWB2);   // 6144 / 4352
    constexpr int STAGE = 2 * 128 * AROWB + 2 * BHALF;             // 24576 / 20992
    constexpr int AH = 0, AL = 128 * AROWB, BH = 2 * 128 * AROWB, BL = BH + BHALF;

    __shared__ __align__(16) char sm[2 * STAGE];
    const uint32_t sb = smem_u32(sm);

    const int tid  = threadIdx.x;
    const int lane = tid & 31;
    const int warp = tid >> 5;         // 0..3
    const int wm   = warp & 1;         // m offset 64*wm
    const int wn   = warp >> 1;        // n offset 64*wn (0..1)
    const int b  = blockIdx.z;
    const int yT = blockIdx.y;
    const int xT = blockIdx.x;

    // DEVICE-SIDE scratch binding
    const float* Abase_f = actx + ((size_t)b * LC + (size_t)yT * 128) * DIM;  // GEMM1 A
    const char*  Awh = (const char*)g_w_hi + ((size_t)b * LC + (size_t)yT * 128) * LQ * 2;
    const char*  Awl = (const char*)g_w_lo + ((size_t)b * LC + (size_t)yT * 128) * LQ * 2;
    const char *Bqh, *Bql;
    if (FIRST) {   // B rows = q index (k-major)
        Bqh = (const char*)g_q_hi + ((size_t)b * LQ + (size_t)xT * 128) * DIM * 2;
        Bql = (const char*)g_q_lo + ((size_t)b * LQ + (size_t)xT * 128) * DIM * 2;
    } else {       // B = [k=q][n=d]
        Bqh = (const char*)g_q_hi + ((size_t)b * LQ * DIM + (size_t)xT * 128) * 2;
        Bql = (const char*)g_q_lo + ((size_t)b * LQ * DIM + (size_t)xT * 128) * 2;
    }

    // ---- loader coordinates (128 threads) ----
    const int ar  = tid >> 2, ac = tid & 3;         // GEMM1 A fp32: rows ar+32i, 16B chunk ac
    const int kr2 = tid >> 4, nc2 = (tid & 15) * 16; // GEMM2 B: k-rows kr2, kr2+8

    // prefetch registers
    float4 pa[4];                 // GEMM1 A fp32 (rows ar, ar+32, ar+64, ar+96)
    uint4  pah0, pah1, pal0, pal1;  // bf16 A row tid, 2 chunks   (GEMM2) / B row tid (GEMM1)
    uint4  pbh0, pbh1, pbl0, pbl1;  // GEMM2 B / unused extra for GEMM1

    auto ldg_tiles = [&](int kt) {
        if (FIRST) {
#pragma unroll
            for (int i = 0; i < 4; i++)
                pa[i] = *(const float4*)(Abase_f + (size_t)(ar + 32 * i) * DIM + kt * 16 + ac * 4);
            const size_t g = (size_t)tid * (DIM * 2) + (size_t)kt * 32;
            pah0 = *(const uint4*)(Bqh + g);      pah1 = *(const uint4*)(Bqh + g + 16);
            pal0 = *(const uint4*)(Bql + g);      pal1 = *(const uint4*)(Bql + g + 16);
        } else {
            const size_t ga = (size_t)tid * (LQ * 2) + (size_t)kt * 32;
            pah0 = *(const uint4*)(Awh + ga);     pah1 = *(const uint4*)(Awh + ga + 16);
            pal0 = *(const uint4*)(Awl + ga);     pal1 = *(const uint4*)(Awl + ga + 16);
            const size_t gb0 = (size_t)(kt * 16 + kr2) * (DIM * 2) + nc2;
            const size_t gb1 = (size_t)(kt * 16 + kr2 + 8) * (DIM * 2) + nc2;
            pbh0 = *(const uint4*)(Bqh + gb0);    pbh1 = *(const uint4*)(Bqh + gb1);
            pbl0 = *(const uint4*)(Bql + gb0);    pbl1 = *(const uint4*)(Bql + gb1);
        }
    };
    auto sts_stage = [&](uint32_t s0) {
        if (FIRST) {
            uint32_t h0, h1, l0, l1;
#pragma unroll
            for (int i = 0; i < 4; i++) {
                split4(pa[i], h0, h1, l0, l1);
                *(uint2*)(sm + (s0 + AH + (ar + 32 * i) * AROWB + ac * 8)) = make_uint2(h0, h1);
                *(uint2*)(sm + (s0 + AL + (ar + 32 * i) * AROWB + ac * 8)) = make_uint2(l0, l1);
            }
            *(uint4*)(sm + (s0 + BH + tid * AROWB))      = pah0;
            *(uint4*)(sm + (s0 + BH + tid * AROWB + 16)) = pah1;
            *(uint4*)(sm + (s0 + BL + tid * AROWB))      = pal0;
            *(uint4*)(sm + (s0 + BL + tid * AROWB + 16)) = pal1;
        } else {
            *(uint4*)(sm + (s0 + AH + tid * AROWB))      = pah0;
            *(uint4*)(sm + (s0 + AH + tid * AROWB + 16)) = pah1;
            *(uint4*)(sm + (s0 + AL + tid * AROWB))      = pal0;
            *(uint4*)(sm + (s0 + AL + tid * AROWB + 16)) = pal1;
            *(uint4*)(sm + (s0 + BH + kr2 * BROWB2 + nc2))       = pbh0;
            *(uint4*)(sm + (s0 + BH + (kr2 + 8) * BROWB2 + nc2)) = pbh1;
            *(uint4*)(sm + (s0 + BL + kr2 * BROWB2 + nc2))       = pbl0;
            *(uint4*)(sm + (s0 + BL + (kr2 + 8) * BROWB2 + nc2)) = pbl1;
        }
    };

    float acc[4][8][4];
#pragma unroll
    for (int m = 0; m < 4; m++)
#pragma unroll
        for (int n = 0; n < 8; n++)
#pragma unroll
            for (int j = 0; j < 4; j++) acc[m][n][j] = 0.f;

    // prologue: stage 0
    ldg_tiles(0);
    sts_stage(0);
    __syncthreads();

    const int lrow = lane & 15;
    const int lkb  = lane & 16;         // second 16B chunk (k+8 / n+8)
    constexpr int I1 = FIRST ? 2 : 1;   // ntile0 second b-reg
    constexpr int J0 = FIRST ? 1 : 2;   // ntile1 first b-reg

    for (int kt = 0; kt < NT; kt++) {
        const uint32_t s0 = (kt & 1) * STAGE;

        if (kt + 1 < NT) ldg_tiles(kt + 1);

        uint32_t ahf[4][4], alf[4][4];
#pragma unroll
        for (int mt = 0; mt < 4; mt++) {
            uint32_t ra = sb + s0 + AH + (wm * 64 + mt * 16 + lrow) * AROWB + lkb;
            ldm4(ra, ahf[mt][0], ahf[mt][1], ahf[mt][2], ahf[mt][3]);
            uint32_t rl = sb + s0 + AL + (wm * 64 + mt * 16 + lrow) * AROWB + lkb;
            ldm4(rl, alf[mt][0], alf[mt][1], alf[mt][2], alf[mt][3]);
        }
#pragma unroll
        for (int p = 0; p < 4; p++) {   // 4 n16 groups -> 8 n8 tiles (warp n=64)
            uint32_t bh[4], bl[4];
            if (FIRST) {
                uint32_t rb = sb + s0 + BH + (wn * 64 + p * 16 + lrow) * AROWB + lkb;
                ldm4(rb, bh[0], bh[1], bh[2], bh[3]);
                uint32_t rc = sb + s0 + BL + (wn * 64 + p * 16 + lrow) * AROWB + lkb;
                ldm4(rc, bl[0], bl[1], bl[2], bl[3]);
            } else {
                uint32_t rb = sb + s0 + BH + lrow * BROWB2 + (wn * 64 + p * 16) * 2 + lkb;
                ldm4t(rb, bh[0], bh[1], bh[2], bh[3]);
                uint32_t rc = sb + s0 + BL + lrow * BROWB2 + (wn * 64 + p * 16) * 2 + lkb;
                ldm4t(rc, bl[0], bl[1], bl[2], bl[3]);
            }
#pragma unroll
            for (int mt = 0; mt < 4; mt++) {
                mma16816(acc[mt][2 * p],     ahf[mt][0], ahf[mt][1], ahf[mt][2], ahf[mt][3], bh[0],  bh[I1]);
                mma16816(acc[mt][2 * p + 1], ahf[mt][0], ahf[mt][1], ahf[mt][2], ahf[mt][3], bh[J0], bh[3]);
                mma16816(acc[mt][2 * p],     alf[mt][0], alf[mt][1], alf[mt][2], alf[mt][3], bh[0],  bh[I1]);
                mma16816(acc[mt][2 * p + 1], alf[mt][0], alf[mt][1], alf[mt][2], alf[mt][3], bh[J0], bh[3]);
                mma16816(acc[mt][2 * p],     ahf[mt][0], ahf[mt][1], ahf[mt][2], ahf[mt][3], bl[0],  bl[I1]);
                mma16816(acc[mt][2 * p + 1], ahf[mt][0], ahf[mt][1], ahf[mt][2], ahf[mt][3], bl[J0], bl[3]);
            }
        }

        if (kt + 1 < NT) sts_stage(((kt + 1) & 1) * STAGE);
        __syncthreads();
    }

    // ---- epilogue (standard m16n8 C layout) ----
    float* Cg = FIRST ? (float*)g_attn : gout;
    const size_t rbase = (size_t)b * LC + (size_t)yT * 128 + wm * 64 + (lane >> 2);
    const int    cbase = OUTOFF + xT * 128 + wn * 64 + (lane & 3) * 2;
#pragma unroll
    for (int mt = 0; mt < 4; mt++) {
#pragma unroll
        for (int nt = 0; nt < 8; nt++) {
            size_t r0 = (rbase + mt * 16) * OUTSTRIDE + cbase + nt * 8;
            *(float2*)(Cg + r0)                    = make_float2(acc[mt][nt][0], acc[mt][nt][1]);
            *(float2*)(Cg + r0 + 8ull * OUTSTRIDE) = make_float2(acc[mt][nt][2], acc[mt][nt][3]);
        }
    }

    // fused ctx copy into out LEFT half (GEMM2 only): this CTA's 128x128 tile
    if (!FIRST) {
        const float4* csrc = (const float4*)(actx + ((size_t)b * LC + (size_t)yT * 128) * DIM
                                             + (size_t)xT * 128);
        float4* cdst = (float4*)(gout + ((size_t)b * LC + (size_t)yT * 128) * (2 * DIM)
                                 + (size_t)xT * 128);
        const int crow = tid >> 5;      // 0..3
        const int ccol = tid & 31;      // 32 float4 = 128 floats
#pragma unroll
        for (int it = 0; it < 32; it++) {
            cdst[(size_t)(crow + it * 4) * (2 * DIM / 4) + ccol] =
                csrc[(size_t)(crow + it * 4) * (DIM / 4) + ccol];
        }
    }
}

// ---------------------------------------------------------------------------
// Warp-per-row softmax over 512 logits: fp32 in (g_attn), bf16 hi/lo out (g_w).
// ---------------------------------------------------------------------------
__global__ __launch_bounds__(256)
void ba_softmax(void)
{
    const int wid = threadIdx.x >> 5, lane = threadIdx.x & 31;
    const size_t row = (size_t)blockIdx.x * 8 + wid;
    const float4* p = (const float4*)(g_attn + row * LQ);

    float4 v[4];
    float mx = -1e30f;
#pragma unroll
    for (int i = 0; i < 4; i++) {
        v[i] = p[i * 32 + lane];
        mx = fmaxf(mx, fmaxf(fmaxf(v[i].x, v[i].y), fmaxf(v[i].z, v[i].w)));
    }
#pragma unroll
    for (int o = 16; o > 0; o >>= 1) mx = fmaxf(mx, __shfl_xor_sync(0xFFFFFFFFu, mx, o));

    float sum = 0.f;
#pragma unroll
    for (int i = 0; i < 4; i++) {
        v[i].x = __expf(v[i].x - mx); v[i].y = __expf(v[i].y - mx);
        v[i].z = __expf(v[i].z - mx); v[i].w = __expf(v[i].w - mx);
        sum += (v[i].x + v[i].y) + (v[i].z + v[i].w);
    }
#pragma unroll
    for (int o = 16; o > 0; o >>= 1) sum += __shfl_xor_sync(0xFFFFFFFFu, sum, o);

    const float inv = 1.0f / sum;
    uint2* ph = (uint2*)(g_w_hi + row * LQ);
    uint2* pl = (uint2*)(g_w_lo + row * LQ);
#pragma unroll
    for (int i = 0; i < 4; i++) {
        v[i].x *= inv; v[i].y *= inv; v[i].z *= inv; v[i].w *= inv;
        uint32_t h01, h23, l01, l23;
        split4(v[i], h01, h23, l01, l23);
        ph[i * 32 + lane] = make_uint2(h01, h23);
        pl[i * 32 + lane] = make_uint2(l01, l23);
    }
}

// ---------------------------------------------------------------------------
extern "C" void kernel_launch(void* const* d_in, const int* in_sizes, int n_in,
                              void* d_out, int out_size)
{
    const float* question = (const float*)d_in[0];
    const float* context  = (const float*)d_in[1];
    if (in_sizes[0] > in_sizes[1]) {
        const float* t = question; question = context; context = t;
    }
    float* out = (float*)d_out;

    // pre-split Q (small, ~6us)
    ba_split_q<<<(size_t)BATCH * LQ * DIM / 4 / 256, 256>>>(question);

    // logits = ctx @ q^T -> g_attn
    ba_mma<true><<<dim3(LQ / 128, LC / 128, BATCH), 128>>>(context, nullptr);
    // softmax -> bf16 hi/lo weights
    ba_softmax<<<BATCH * LC / 8, 256>>>();
    // attn_out = w @ q -> right half of out, + fused ctx copy -> left half
    ba_mma<false><<<dim3(DIM / 128, LC / 128, BATCH), 128>>>(context, out);
}

// round 14
// speedup vs baseline: 1.5592x; 1.2992x over previous
#include <cuda_runtime.h>
#include <cuda_bf16.h>
#include <cuda_fp16.h>
#include <cstdint>

#define BATCH 16
#define LQ    512
#define LC    2048
#define DIM   1024

// ---------------------------------------------------------------------------
// Device scratch (device-side only; symbols NEVER passed from host)
// ---------------------------------------------------------------------------
__device__ float         g_attn[(size_t)BATCH * LC * LQ];     // fp32 logits
__device__ __nv_bfloat16 g_q_hi[(size_t)BATCH * LQ * DIM];
__device__ __nv_bfloat16 g_q_lo[(size_t)BATCH * LQ * DIM];
__device__ __half        g_q16 [(size_t)BATCH * LQ * DIM];    // fp16 q  (GEMM2)
__device__ __half        g_w16 [(size_t)BATCH * LC * LQ];     // fp16 softmax weights

// ---------------------------------------------------------------------------
// helpers
// ---------------------------------------------------------------------------
__device__ __forceinline__ void ldm4(uint32_t a, uint32_t& r0, uint32_t& r1,
                                     uint32_t& r2, uint32_t& r3) {
    asm volatile("ldmatrix.sync.aligned.m8n8.x4.shared.b16 {%0,%1,%2,%3}, [%4];"
                 : "=r"(r0), "=r"(r1), "=r"(r2), "=r"(r3) : "r"(a));
}
__device__ __forceinline__ void ldm4t(uint32_t a, uint32_t& r0, uint32_t& r1,
                                      uint32_t& r2, uint32_t& r3) {
    asm volatile("ldmatrix.sync.aligned.m8n8.x4.trans.shared.b16 {%0,%1,%2,%3}, [%4];"
                 : "=r"(r0), "=r"(r1), "=r"(r2), "=r"(r3) : "r"(a));
}
__device__ __forceinline__ void mma16816(float* c, uint32_t a0, uint32_t a1, uint32_t a2,
                                         uint32_t a3, uint32_t b0, uint32_t b1) {
    asm volatile(
        "mma.sync.aligned.m16n8k16.row.col.f32.bf16.bf16.f32 "
        "{%0,%1,%2,%3}, {%4,%5,%6,%7}, {%8,%9}, {%0,%1,%2,%3};"
        : "+f"(c[0]), "+f"(c[1]), "+f"(c[2]), "+f"(c[3])
        : "r"(a0), "r"(a1), "r"(a2), "r"(a3), "r"(b0), "r"(b1));
}
__device__ __forceinline__ void mma16816h(float* c, uint32_t a0, uint32_t a1, uint32_t a2,
                                          uint32_t a3, uint32_t b0, uint32_t b1) {
    asm volatile(
        "mma.sync.aligned.m16n8k16.row.col.f32.f16.f16.f32 "
        "{%0,%1,%2,%3}, {%4,%5,%6,%7}, {%8,%9}, {%0,%1,%2,%3};"
        : "+f"(c[0]), "+f"(c[1]), "+f"(c[2]), "+f"(c[3])
        : "r"(a0), "r"(a1), "r"(a2), "r"(a3), "r"(b0), "r"(b1));
}
__device__ __forceinline__ uint32_t smem_u32(const void* p) {
    uint32_t a;
    asm("{ .reg .u64 t; cvta.to.shared.u64 t, %1; cvt.u32.u64 %0, t; }" : "=r"(a) : "l"(p));
    return a;
}
// split float4 into packed bf16 hi pair-words and lo pair-words
__device__ __forceinline__ void split4(float4 v, uint32_t& h01, uint32_t& h23,
                                       uint32_t& l01, uint32_t& l23) {
    __nv_bfloat16 hx = __float2bfloat16(v.x), hy = __float2bfloat16(v.y);
    __nv_bfloat16 hz = __float2bfloat16(v.z), hw = __float2bfloat16(v.w);
    float lx = v.x - __bfloat162float(hx), ly = v.y - __bfloat162float(hy);
    float lz = v.z - __bfloat162float(hz), lw = v.w - __bfloat162float(hw);
    __nv_bfloat162 H0(hx, hy), H1(hz, hw);
    __nv_bfloat162 L0 = __floats2bfloat162_rn(lx, ly), L1 = __floats2bfloat162_rn(lz, lw);
    h01 = *(uint32_t*)&H0; h23 = *(uint32_t*)&H1;
    l01 = *(uint32_t*)&L0; l23 = *(uint32_t*)&L1;
}
// pack float4 -> two half2 words
__device__ __forceinline__ uint2 pack4h(float4 v) {
    __half2 a(__float2half_rn(v.x), __float2half_rn(v.y));
    __half2 b(__float2half_rn(v.z), __float2half_rn(v.w));
    return make_uint2(*(uint32_t*)&a, *(uint32_t*)&b);
}

// ---------------------------------------------------------------------------
// Q pre-split: fp32 -> bf16 hi/lo (GEMM1) + fp16 (GEMM2)
// ---------------------------------------------------------------------------
__global__ __launch_bounds__(256)
void ba_split_q(const float* __restrict__ src)
{
    const size_t i = (size_t)blockIdx.x * 256 + threadIdx.x;   // float4 index
    float4 v = ((const float4*)src)[i];
    uint32_t h01, h23, l01, l23;
    split4(v, h01, h23, l01, l23);
    ((uint2*)g_q_hi)[i] = make_uint2(h01, h23);
    ((uint2*)g_q_lo)[i] = make_uint2(l01, l23);
    ((uint2*)g_q16)[i]  = pack4h(v);
}

// ---------------------------------------------------------------------------
// GEMM1 (R11 verbatim specialization): logits = ctx @ q^T -> g_attn
// Split-bf16 (3 MMAs), CTA 128x128, 256 thr, warp 64x32, BK=16, double-buffered.
// ---------------------------------------------------------------------------
#define AROWB 48                   // 16 bf16 = 32B + 16B pad (conflict-free)

__global__ __launch_bounds__(256, 2)
void ba_gemm1(const float* __restrict__ actx)
{
    constexpr int KT = DIM;
    constexpr int NT = KT / 16;
    constexpr int STAGE = 4 * 128 * AROWB;                         // 24576
    constexpr int AH = 0, AL = 128 * AROWB, BH = 2 * 128 * AROWB, BL = 3 * 128 * AROWB;

    __shared__ __align__(16) char sm[2 * STAGE];
    const uint32_t sb = smem_u32(sm);

    const int tid  = threadIdx.x;
    const int lane = tid & 31;
    const int warp = tid >> 5;
    const int wm   = warp & 1;
    const int wn   = warp >> 1;        // 0..3, n offset 32*wn
    const int b  = blockIdx.z;
    const int yT = blockIdx.y;
    const int xT = blockIdx.x;

    const float* Abase_f = actx + ((size_t)b * LC + (size_t)yT * 128) * DIM;
    const char* Bqh = (const char*)g_q_hi + ((size_t)b * LQ + (size_t)xT * 128) * DIM * 2;
    const char* Bql = (const char*)g_q_lo + ((size_t)b * LQ + (size_t)xT * 128) * DIM * 2;

    const int ar = tid >> 2, ac = tid & 3;          // A fp32: rows ar, ar+64
    const int br = tid >> 1, bc = (tid & 1) * 16;   // B bf16: row br, 16B chunk

    float4 pa0, pa1;
    uint4  pbh, pbl;

    auto ldg_tiles = [&](int kt) {
        pa0 = *(const float4*)(Abase_f + (size_t)ar * DIM + kt * 16 + ac * 4);
        pa1 = *(const float4*)(Abase_f + (size_t)(ar + 64) * DIM + kt * 16 + ac * 4);
        pbh = *(const uint4*)(Bqh + (size_t)br * (DIM * 2) + kt * 32 + bc);
        pbl = *(const uint4*)(Bql + (size_t)br * (DIM * 2) + kt * 32 + bc);
    };
    auto sts_stage = [&](uint32_t s0) {
        uint32_t h0, h1, l0, l1;
        split4(pa0, h0, h1, l0, l1);
        *(uint2*)(sm + (s0 + AH + ar * AROWB + ac * 8))        = make_uint2(h0, h1);
        *(uint2*)(sm + (s0 + AL + ar * AROWB + ac * 8))        = make_uint2(l0, l1);
        split4(pa1, h0, h1, l0, l1);
        *(uint2*)(sm + (s0 + AH + (ar + 64) * AROWB + ac * 8)) = make_uint2(h0, h1);
        *(uint2*)(sm + (s0 + AL + (ar + 64) * AROWB + ac * 8)) = make_uint2(l0, l1);
        *(uint4*)(sm + (s0 + BH + br * AROWB + bc)) = pbh;
        *(uint4*)(sm + (s0 + BL + br * AROWB + bc)) = pbl;
    };

    float acc[4][4][4];
#pragma unroll
    for (int m = 0; m < 4; m++)
#pragma unroll
        for (int n = 0; n < 4; n++)
#pragma unroll
            for (int j = 0; j < 4; j++) acc[m][n][j] = 0.f;

    ldg_tiles(0);
    sts_stage(0);
    __syncthreads();

    const int lrow = lane & 15;
    const int lkb  = lane & 16;

    for (int kt = 0; kt < NT; kt++) {
        const uint32_t s0 = (kt & 1) * STAGE;
        if (kt + 1 < NT) ldg_tiles(kt + 1);

        uint32_t ahf[4][4], alf[4][4];
#pragma unroll
        for (int mt = 0; mt < 4; mt++) {
            uint32_t ra = sb + s0 + AH + (wm * 64 + mt * 16 + lrow) * AROWB + lkb;
            ldm4(ra, ahf[mt][0], ahf[mt][1], ahf[mt][2], ahf[mt][3]);
            uint32_t rl = sb + s0 + AL + (wm * 64 + mt * 16 + lrow) * AROWB + lkb;
            ldm4(rl, alf[mt][0], alf[mt][1], alf[mt][2], alf[mt][3]);
        }
#pragma unroll
        for (int p = 0; p < 2; p++) {
            uint32_t bh[4], bl[4];
            uint32_t rb = sb + s0 + BH + (wn * 32 + p * 16 + lrow) * AROWB + lkb;
            ldm4(rb, bh[0], bh[1], bh[2], bh[3]);
            uint32_t rc = sb + s0 + BL + (wn * 32 + p * 16 + lrow) * AROWB + lkb;
            ldm4(rc, bl[0], bl[1], bl[2], bl[3]);
#pragma unroll
            for (int mt = 0; mt < 4; mt++) {
                mma16816(acc[mt][2 * p],     ahf[mt][0], ahf[mt][1], ahf[mt][2], ahf[mt][3], bh[0], bh[2]);
                mma16816(acc[mt][2 * p + 1], ahf[mt][0], ahf[mt][1], ahf[mt][2], ahf[mt][3], bh[1], bh[3]);
                mma16816(acc[mt][2 * p],     alf[mt][0], alf[mt][1], alf[mt][2], alf[mt][3], bh[0], bh[2]);
                mma16816(acc[mt][2 * p + 1], alf[mt][0], alf[mt][1], alf[mt][2], alf[mt][3], bh[1], bh[3]);
                mma16816(acc[mt][2 * p],     ahf[mt][0], ahf[mt][1], ahf[mt][2], ahf[mt][3], bl[0], bl[2]);
                mma16816(acc[mt][2 * p + 1], ahf[mt][0], ahf[mt][1], ahf[mt][2], ahf[mt][3], bl[1], bl[3]);
            }
        }

        if (kt + 1 < NT) sts_stage(((kt + 1) & 1) * STAGE);
        __syncthreads();
    }

    float* Cg = (float*)g_attn;
    const size_t rbase = (size_t)b * LC + (size_t)yT * 128 + wm * 64 + (lane >> 2);
    const int    cbase = xT * 128 + wn * 32 + (lane & 3) * 2;
#pragma unroll
    for (int mt = 0; mt < 4; mt++) {
#pragma unroll
        for (int nt = 0; nt < 4; nt++) {
            size_t r0 = (rbase + mt * 16) * LQ + cbase + nt * 8;
            *(float2*)(Cg + r0)             = make_float2(acc[mt][nt][0], acc[mt][nt][1]);
            *(float2*)(Cg + r0 + 8ull * LQ) = make_float2(acc[mt][nt][2], acc[mt][nt][3]);
        }
    }
}

// ---------------------------------------------------------------------------
// GEMM2 (fp16 single-MMA): attn[c][d] = w16[c][q] . q16[q][d]  -> out right half
//        + fused ctx 128x128 tile copy into out LEFT half.
// CTA 128x128, 256 thr, warp 64x32, BK=16, double-buffered static smem.
// Precision: w,q in fp16 (rel ~2^-11) -> attn-half err ~2e-4, total ~1.4e-4.
// ---------------------------------------------------------------------------
#define BROWB2 272                 // B rows: 128 fp16 = 256B + 16B pad

__global__ __launch_bounds__(256, 2)
void ba_gemm2(const float* __restrict__ actx, float* __restrict__ gout)
{
    constexpr int NT = LQ / 16;                                    // 32
    constexpr int STAGE = 128 * AROWB + 16 * BROWB2;               // 6144+4352=10496
    constexpr int AOFF = 0, BOFF = 128 * AROWB;

    __shared__ __align__(16) char sm[2 * STAGE];
    const uint32_t sb = smem_u32(sm);

    const int tid  = threadIdx.x;
    const int lane = tid & 31;
    const int warp = tid >> 5;
    const int wm   = warp & 1;
    const int wn   = warp >> 1;        // 0..3, n offset 32*wn
    const int b  = blockIdx.z;
    const int yT = blockIdx.y;
    const int xT = blockIdx.x;

    const char* Aw = (const char*)g_w16 + ((size_t)b * LC + (size_t)yT * 128) * LQ * 2;
    const char* Bq = (const char*)g_q16 + ((size_t)b * LQ * DIM + (size_t)xT * 128) * 2;

    const int ar2 = tid >> 1, ac2 = (tid & 1) * 16;   // A: 128 rows x 32B
    const int kr2 = tid >> 4, nc2 = (tid & 15) * 16;  // B: 16 k-rows x 256B

    uint4 pa, pb;
    auto ldg_tiles = [&](int kt) {
        pa = *(const uint4*)(Aw + (size_t)ar2 * (LQ * 2) + kt * 32 + ac2);
        pb = *(const uint4*)(Bq + (size_t)(kt * 16 + kr2) * (DIM * 2) + nc2);
    };
    auto sts_stage = [&](uint32_t s0) {
        *(uint4*)(sm + (s0 + AOFF + ar2 * AROWB + ac2)) = pa;
        *(uint4*)(sm + (s0 + BOFF + kr2 * BROWB2 + nc2)) = pb;
    };

    float acc[4][4][4];
#pragma unroll
    for (int m = 0; m < 4; m++)
#pragma unroll
        for (int n = 0; n < 4; n++)
#pragma unroll
            for (int j = 0; j < 4; j++) acc[m][n][j] = 0.f;

    ldg_tiles(0);
    sts_stage(0);
    __syncthreads();

    const int lrow = lane & 15;
    const int lkb  = lane & 16;

    for (int kt = 0; kt < NT; kt++) {
        const uint32_t s0 = (kt & 1) * STAGE;
        if (kt + 1 < NT) ldg_tiles(kt + 1);

        uint32_t af[4][4];
#pragma unroll
        for (int mt = 0; mt < 4; mt++) {
            uint32_t ra = sb + s0 + AOFF + (wm * 64 + mt * 16 + lrow) * AROWB + lkb;
            ldm4(ra, af[mt][0], af[mt][1], af[mt][2], af[mt][3]);
        }
#pragma unroll
        for (int p = 0; p < 2; p++) {
            uint32_t bh[4];
            uint32_t rb = sb + s0 + BOFF + lrow * BROWB2 + (wn * 32 + p * 16) * 2 + lkb;
            ldm4t(rb, bh[0], bh[1], bh[2], bh[3]);
#pragma unroll
            for (int mt = 0; mt < 4; mt++) {
                mma16816h(acc[mt][2 * p],     af[mt][0], af[mt][1], af[mt][2], af[mt][3], bh[0], bh[1]);
                mma16816h(acc[mt][2 * p + 1], af[mt][0], af[mt][1], af[mt][2], af[mt][3], bh[2], bh[3]);
            }
        }

        if (kt + 1 < NT) sts_stage(((kt + 1) & 1) * STAGE);
        __syncthreads();
    }

    // epilogue -> out right half
    const size_t rbase = (size_t)b * LC + (size_t)yT * 128 + wm * 64 + (lane >> 2);
    const int    cbase = DIM + xT * 128 + wn * 32 + (lane & 3) * 2;
#pragma unroll
    for (int mt = 0; mt < 4; mt++) {
#pragma unroll
        for (int nt = 0; nt < 4; nt++) {
            size_t r0 = (rbase + mt * 16) * (2 * DIM) + cbase + nt * 8;
            *(float2*)(gout + r0)                    = make_float2(acc[mt][nt][0], acc[mt][nt][1]);
            *(float2*)(gout + r0 + 8ull * (2 * DIM)) = make_float2(acc[mt][nt][2], acc[mt][nt][3]);
        }
    }

    // fused ctx copy into out LEFT half: this CTA's 128x128 tile
    {
        const float4* csrc = (const float4*)(actx + ((size_t)b * LC + (size_t)yT * 128) * DIM
                                             + (size_t)xT * 128);
        float4* cdst = (float4*)(gout + ((size_t)b * LC + (size_t)yT * 128) * (2 * DIM)
                                 + (size_t)xT * 128);
        const int crow = tid >> 5;      // 0..7
        const int ccol = tid & 31;      // 32 float4 = 128 floats
#pragma unroll
        for (int it = 0; it < 16; it++) {
            cdst[(size_t)(crow + it * 8) * (2 * DIM / 4) + ccol] =
                csrc[(size_t)(crow + it * 8) * (DIM / 4) + ccol];
        }
    }
}

// ---------------------------------------------------------------------------
// Warp-per-row softmax over 512 logits: fp32 in (g_attn), fp16 out (g_w16).
// ---------------------------------------------------------------------------
__global__ __launch_bounds__(256)
void ba_softmax(void)
{
    const int wid = threadIdx.x >> 5, lane = threadIdx.x & 31;
    const size_t row = (size_t)blockIdx.x * 8 + wid;
    const float4* p = (const float4*)(g_attn + row * LQ);

    float4 v[4];
    float mx = -1e30f;
#pragma unroll
    for (int i = 0; i < 4; i++) {
        v[i] = p[i * 32 + lane];
        mx = fmaxf(mx, fmaxf(fmaxf(v[i].x, v[i].y), fmaxf(v[i].z, v[i].w)));
    }
#pragma unroll
    for (int o = 16; o > 0; o >>= 1) mx = fmaxf(mx, __shfl_xor_sync(0xFFFFFFFFu, mx, o));

    float sum = 0.f;
#pragma unroll
    for (int i = 0; i < 4; i++) {
        v[i].x = __expf(v[i].x - mx); v[i].y = __expf(v[i].y - mx);
        v[i].z = __expf(v[i].z - mx); v[i].w = __expf(v[i].w - mx);
        sum += (v[i].x + v[i].y) + (v[i].z + v[i].w);
    }
#pragma unroll
    for (int o = 16; o > 0; o >>= 1) sum += __shfl_xor_sync(0xFFFFFFFFu, sum, o);

    const float inv = 1.0f / sum;
    uint2* pw = (uint2*)(g_w16 + row * LQ);
#pragma unroll
    for (int i = 0; i < 4; i++) {
        v[i].x *= inv; v[i].y *= inv; v[i].z *= inv; v[i].w *= inv;
        pw[i * 32 + lane] = pack4h(v[i]);
    }
}

// ---------------------------------------------------------------------------
extern "C" void kernel_launch(void* const* d_in, const int* in_sizes, int n_in,
                              void* d_out, int out_size)
{
    const float* question = (const float*)d_in[0];
    const float* context  = (const float*)d_in[1];
    if (in_sizes[0] > in_sizes[1]) {
        const float* t = question; question = context; context = t;
    }
    float* out = (float*)d_out;

    // pre-split Q (bf16 hi/lo for GEMM1, fp16 for GEMM2)
    ba_split_q<<<(size_t)BATCH * LQ * DIM / 4 / 256, 256>>>(question);

    // logits = ctx @ q^T -> g_attn (3-MMA bf16 split)
    ba_gemm1<<<dim3(LQ / 128, LC / 128, BATCH), 256>>>(context);
    // softmax -> fp16 weights
    ba_softmax<<<BATCH * LC / 8, 256>>>();
    // attn_out = w16 @ q16 (single fp16 MMA) -> right half, + fused ctx copy
    ba_gemm2<<<dim3(DIM / 128, LC / 128, BATCH), 256>>>(context, out);
}